// round 11
// baseline (speedup 1.0000x reference)
#include <cuda_runtime.h>
#include <cuda_fp16.h>
#include <cuda_bf16.h>
#include <cstdint>

// ---------------- problem constants ----------------
#define NB   64
#define NT   256
#define NC   256
#define HW   4096
#define NITER 30

#define K2C     28.853900817779268f   // log2(e)/eps
#define INV_K2  0.03465735902799727f  // eps*ln2
#define SHIFTF  26.0f
#define MUC     (1.0f/256.0f)

// ---------------- scratch ----------------
__device__ __align__(16) __nv_bfloat16 g_samp[(size_t)2 * NB * NC * NT]; // [z][b][c][i]
__device__ __align__(16) __nv_bfloat16 g_tok[(size_t)2 * NB * NT * NC];  // [z][b][i][c]
__device__ __align__(16) __half        g_K[(size_t)NB * NT * NT];
__device__ float    g_part[2 * NB];
__device__ unsigned g_ctr;

__device__ __forceinline__ uint32_t smem_u32(const void* p) {
    uint32_t a;
    asm("{ .reg .u64 t; cvta.to.shared.u64 t, %1; cvt.u32.u64 %0, t; }" : "=r"(a) : "l"(p));
    return a;
}
__device__ __forceinline__ uint32_t h2_as_u32(__half lo, __half hi) {
    union { __half2 h; uint32_t u; } c;
    c.h = __halves2half2(lo, hi);
    return c.u;
}

// ============================================================================
// Kernel 1: fully-coalesced streaming sampler (ldcs: no-reuse streaming).
// ============================================================================
__global__ __launch_bounds__(256) void sample_kernel(
    const float* __restrict__ pred, const float* __restrict__ tgt)
{
    const int b = blockIdx.x, z = blockIdx.y;
    if (threadIdx.x == 0 && (b | z | blockIdx.z) == 0) g_ctr = 0u;

    const int tid = threadIdx.x;
    const float DELTA = 4095.0f / 255.0f;

    #pragma unroll
    for (int q = 0; q < 4; ++q) {
        const int c = blockIdx.z * 4 + q;
        const float4* __restrict__ plane =
            (const float4*)(((z ? tgt : pred)) + ((size_t)b * NC + c) * HW);
        __nv_bfloat16* __restrict__ dst = g_samp + (((size_t)z * NB + b) * NC + c) * NT;

        float4 f[4];
        #pragma unroll
        for (int k = 0; k < 4; ++k) f[k] = __ldcs(&plane[tid + k * 256]);

        #pragma unroll
        for (int k = 0; k < 4; ++k) {
            const int p4 = (tid + k * 256) * 4;              // window [p4, p4+4)
            const int cand = (int)(__fdividef((float)(p4 + 2), DELTA));
            #pragma unroll
            for (int d = -1; d <= 1; ++d) {
                const int i = cand + d;
                if (i >= 0 && i < 256) {
                    const int s = (int)(__fmul_rn((float)i, DELTA));  // exact ref trunc
                    if (s >= p4 && s < p4 + 4) {
                        const float* fv = (const float*)&f[k];
                        dst[i] = __float2bfloat16(fv[s - p4]);
                    }
                }
            }
        }
    }
}

// ============================================================================
// Kernel 2: per-(z,b) l2-normalize + transpose [c][i] -> [i][c] (bf16).
// ============================================================================
#define TSTR 264
#define NTR_SMEM (256 * TSTR * 2 + 4096 + 1024)

__global__ __launch_bounds__(1024, 1) void norm_transpose_kernel()
{
    extern __shared__ unsigned char sm[];
    __half* T   = (__half*)sm;
    float*  pss = (float*)(sm + 256 * TSTR * 2);
    float*  inv = (float*)(sm + 256 * TSTR * 2 + 4096);

    const int zb  = blockIdx.x;
    const int tid = threadIdx.x;

    const uint4* __restrict__ src = (const uint4*)(g_samp + (size_t)zb * NC * NT);
    #pragma unroll
    for (int k = 0; k < 8; ++k) {
        const int idx = tid + k * 1024;
        const int c = idx >> 5, ib = idx & 31;
        *(uint4*)(T + c * TSTR + ((ib ^ ((c >> 3) & 7)) << 3)) = src[idx];
    }
    __syncthreads();

    {
        const int i = tid & 255, part = tid >> 8;
        const int ib = i >> 3, io = i & 7;
        float ss = 0.0f;
        #pragma unroll 8
        for (int cc = 0; cc < 64; ++cc) {
            const int c = part * 64 + cc;
            const float x = __bfloat162float(
                ((const __nv_bfloat16*)T)[c * TSTR + ((ib ^ ((c >> 3) & 7)) << 3) + io]);
            ss = fmaf(x, x, ss);
        }
        pss[part * 256 + i] = ss;
    }
    __syncthreads();
    if (tid < 256) {
        const float ss = pss[tid] + pss[256 + tid] + pss[512 + tid] + pss[768 + tid];
        inv[tid] = __fdividef(1.0f, fmaxf(sqrtf(ss), 1e-12f));
    }
    __syncthreads();

    uint4* __restrict__ dst = (uint4*)(g_tok + (size_t)zb * NT * NC);
    #pragma unroll
    for (int k = 0; k < 8; ++k) {
        const int idx = tid + k * 1024;
        const int i = idx >> 5, c0 = (idx & 31) * 8;
        const float sc = inv[i];
        const int ib = i >> 3, io = i & 7;
        union { uint4 u; __nv_bfloat16 h[8]; } o;
        #pragma unroll
        for (int j = 0; j < 8; ++j) {
            const int c = c0 + j;
            const float x = __bfloat162float(
                ((const __nv_bfloat16*)T)[c * TSTR + ((ib ^ ((c >> 3) & 7)) << 3) + io]);
            o.h[j] = __float2bfloat16(x * sc);
        }
        dst[idx] = o.u;
    }
}

// ============================================================================
// Kernel 3: cost GEMM via mma.sync bf16 (unchanged).
// ============================================================================
#define SPAD 264
#define COST_SMEM ((128 + 256) * SPAD * 2)

__device__ __forceinline__ void mma16816bf(float* c, uint32_t a0, uint32_t a1,
                                           uint32_t a2, uint32_t a3,
                                           uint32_t b0, uint32_t b1) {
    asm volatile(
        "mma.sync.aligned.m16n8k16.row.col.f32.bf16.bf16.f32 "
        "{%0,%1,%2,%3}, {%4,%5,%6,%7}, {%8,%9}, {%0,%1,%2,%3};"
        : "+f"(c[0]), "+f"(c[1]), "+f"(c[2]), "+f"(c[3])
        : "r"(a0), "r"(a1), "r"(a2), "r"(a3), "r"(b0), "r"(b1));
}

__global__ __launch_bounds__(256, 1) void cost_kernel()
{
    extern __shared__ char smem[];
    __nv_bfloat16* As = (__nv_bfloat16*)smem;
    __nv_bfloat16* Bs = (__nv_bfloat16*)(smem + 128 * SPAD * 2);

    const int mh = blockIdx.x;
    const int b  = blockIdx.y;
    const int tid = threadIdx.x, w = tid >> 5, lane = tid & 31;

    const uint4* __restrict__ Ag =
        (const uint4*)(g_tok + ((size_t)b * NT + (size_t)mh * 128) * NC);
    #pragma unroll
    for (int it = 0; it < 16; ++it) {
        const int idx = tid + it * 256;
        *(uint4*)(As + (idx >> 5) * SPAD + (idx & 31) * 8) = Ag[idx];
    }
    const uint4* __restrict__ Bg = (const uint4*)(g_tok + ((size_t)(NB + b)) * NT * NC);
    #pragma unroll
    for (int it = 0; it < 32; ++it) {
        const int idx = tid + it * 256;
        *(uint4*)(Bs + (idx >> 5) * SPAD + (idx & 31) * 8) = Bg[idx];
    }
    __syncthreads();

    const int r0 = w * 16;
    const int lr = lane >> 2;
    const int lj = lane & 3;

    const __nv_bfloat16* A0 = As + (r0 + lr) * SPAD + lj * 2;
    const __nv_bfloat16* A8 = A0 + 8 * SPAD;
    const __nv_bfloat16* B0 = Bs + lr * SPAD + lj * 2;

    __half* __restrict__ K0 = g_K + ((size_t)b * NT + (size_t)(mh * 128 + r0 + lr)) * NT;
    __half* __restrict__ K8 = K0 + 8 * NT;

    #pragma unroll
    for (int h = 0; h < 2; ++h) {
        float c[16][4];
        #pragma unroll
        for (int nt = 0; nt < 16; ++nt)
            c[nt][0] = c[nt][1] = c[nt][2] = c[nt][3] = 0.0f;

        #pragma unroll
        for (int kc = 0; kc < 16; ++kc) {
            const int ko = kc * 16;
            const uint32_t a0 = *(const uint32_t*)(A0 + ko);
            const uint32_t a1 = *(const uint32_t*)(A8 + ko);
            const uint32_t a2 = *(const uint32_t*)(A0 + ko + 8);
            const uint32_t a3 = *(const uint32_t*)(A8 + ko + 8);
            #pragma unroll
            for (int nt = 0; nt < 16; ++nt) {
                const __nv_bfloat16* bp = B0 + (h * 128 + nt * 8) * SPAD + ko;
                mma16816bf(c[nt], a0, a1, a2, a3,
                           *(const uint32_t*)bp, *(const uint32_t*)(bp + 8));
            }
        }

        #pragma unroll
        for (int nt = 0; nt < 16; ++nt) {
            const int col = h * 128 + nt * 8 + lj * 2;
            *(__half2*)(K0 + col) = __halves2half2(
                __float2half_rn(exp2f(fmaf(c[nt][0] - 1.0f, K2C, SHIFTF))),
                __float2half_rn(exp2f(fmaf(c[nt][1] - 1.0f, K2C, SHIFTF))));
            *(__half2*)(K8 + col) = __halves2half2(
                __float2half_rn(exp2f(fmaf(c[nt][2] - 1.0f, K2C, SHIFTF))),
                __float2half_rn(exp2f(fmaf(c[nt][3] - 1.0f, K2C, SHIFTF))));
        }
    }
}

// ============================================================================
// Kernel 4: Sinkhorn. Register-resident MMA fragments; cluster exchange via
// DSMEM push + mbarrier handshake (replaces barrier.cluster: ~490cyc -> ~90).
// 2-CTA clusters (128 rows each), 512 threads.
// ============================================================================
#define SK_KS    0
#define SK_PSUM  65536                 // [2][128] f32
#define SK_CSO   (65536 + 1024)        // own colsums [256] f32
#define SK_RECV  (SK_CSO + 1024)       // peer-pushed colsums [2][256] f32
#define SK_V     (SK_RECV + 2048)
#define SK_U     (SK_V + 1024)
#define SK_UH    (SK_U + 512)
#define SK_VH    (SK_UH + 256)
#define SK_RED   (SK_VH + 512)
#define SK_MBAR  (SK_RED + 128)
#define SK_SMEM  (SK_MBAR + 16)

__device__ __forceinline__ void mma16816f(float* c, uint32_t a0, uint32_t a1,
                                          uint32_t a2, uint32_t a3,
                                          uint32_t b0, uint32_t b1) {
    asm volatile(
        "mma.sync.aligned.m16n8k16.row.col.f32.f16.f16.f32 "
        "{%0,%1,%2,%3}, {%4,%5,%6,%7}, {%8,%9}, {%0,%1,%2,%3};"
        : "+f"(c[0]), "+f"(c[1]), "+f"(c[2]), "+f"(c[3])
        : "r"(a0), "r"(a1), "r"(a2), "r"(a3), "r"(b0), "r"(b1));
}

__global__ __launch_bounds__(512, 1) __cluster_dims__(2, 1, 1)
void sinkhorn_kernel(float* __restrict__ out)
{
    extern __shared__ unsigned char sm[];
    __half* Ks   = (__half*)(sm + SK_KS);      // [128][256] local rows
    float*  psum = (float*)(sm + SK_PSUM);
    float*  cso  = (float*)(sm + SK_CSO);
    float*  recv = (float*)(sm + SK_RECV);
    float*  v    = (float*)(sm + SK_V);
    float*  u    = (float*)(sm + SK_U);
    __half* uh   = (__half*)(sm + SK_UH);
    __half* vh   = (__half*)(sm + SK_VH);
    float*  red  = (float*)(sm + SK_RED);

    const int rank = blockIdx.x & 1;
    const int b    = blockIdx.x >> 1;
    const int tid  = threadIdx.x;
    const int w    = tid >> 5, lane = tid & 31;
    const int lr4  = lane >> 2, lj = lane & 3;

    const uint32_t mbar_local = smem_u32(sm + SK_MBAR);
    uint32_t recv_peer, mbar_peer;
    {
        const uint32_t recv_local = smem_u32(recv);
        asm("mapa.shared::cluster.u32 %0, %1, %2;" : "=r"(recv_peer)
            : "r"(recv_local), "r"(rank ^ 1));
        asm("mapa.shared::cluster.u32 %0, %1, %2;" : "=r"(mbar_peer)
            : "r"(mbar_local), "r"(rank ^ 1));
    }

    if (tid == 0) {
        asm volatile("mbarrier.init.shared.b64 [%0], %1;"
                     :: "r"(mbar_local), "r"(64u) : "memory");
    }

    {   // load my 128 rows of K' (64 KB)
        const uint4* gk = (const uint4*)(g_K + ((size_t)b * NT + (size_t)rank * 128) * NT);
        uint4* sk = (uint4*)Ks;
        #pragma unroll
        for (int q = 0; q < 8; ++q) sk[tid + q * 512] = gk[tid + q * 512];
    }
    if (tid < NT) { v[tid] = 1.0f; vh[tid] = __float2half_rn(1.0f); }
    __syncthreads();

    // cluster sync once: peer mbarrier init visible before any remote push
    asm volatile("barrier.cluster.arrive.aligned;" ::: "memory");
    asm volatile("barrier.cluster.wait.aligned;" ::: "memory");

    // ---- preload register fragments (once) ----
    const int rt = w & 7, kh = w >> 3;
    uint32_t afr[8][4];
    #pragma unroll
    for (int t = 0; t < 8; ++t) {
        const int kt = (kh * 8 + t) * 16 + 2 * lj;
        afr[t][0] = *(const uint32_t*)&Ks[(rt * 16 + lr4) * NT + kt];
        afr[t][1] = *(const uint32_t*)&Ks[(rt * 16 + 8 + lr4) * NT + kt];
        afr[t][2] = *(const uint32_t*)&Ks[(rt * 16 + lr4) * NT + kt + 8];
        afr[t][3] = *(const uint32_t*)&Ks[(rt * 16 + 8 + lr4) * NT + kt + 8];
    }
    uint32_t bfr[2][8][2];
    #pragma unroll
    for (int n2 = 0; n2 < 2; ++n2) {
        const int col = (2 * w + n2) * 8 + lr4;
        #pragma unroll
        for (int t = 0; t < 8; ++t) {
            const int k0 = t * 16 + 2 * lj;
            bfr[n2][t][0] = h2_as_u32(Ks[(size_t)k0 * NT + col],
                                      Ks[(size_t)(k0 + 1) * NT + col]);
            bfr[n2][t][1] = h2_as_u32(Ks[(size_t)(k0 + 8) * NT + col],
                                      Ks[(size_t)(k0 + 9) * NT + col]);
        }
    }

    for (int it = 0; it < NITER; ++it) {
        // ---- u-pass: rowsum partials (2 independent chains)
        {
            float ca[4] = {0.f, 0.f, 0.f, 0.f};
            float cb[4] = {0.f, 0.f, 0.f, 0.f};
            #pragma unroll
            for (int t = 0; t < 8; t += 2) {
                const int kt0 = (kh * 8 + t) * 16 + 2 * lj;
                const int kt1 = (kh * 8 + t + 1) * 16 + 2 * lj;
                mma16816f(ca, afr[t][0], afr[t][1], afr[t][2], afr[t][3],
                          *(const uint32_t*)&vh[kt0], *(const uint32_t*)&vh[kt0 + 8]);
                mma16816f(cb, afr[t+1][0], afr[t+1][1], afr[t+1][2], afr[t+1][3],
                          *(const uint32_t*)&vh[kt1], *(const uint32_t*)&vh[kt1 + 8]);
            }
            if (lj == 0) {
                psum[kh * 128 + rt * 16 + lr4]     = ca[0] + cb[0];
                psum[kh * 128 + rt * 16 + 8 + lr4] = ca[2] + cb[2];
            }
        }
        __syncthreads();
        if (tid < 128) {
            const float s = psum[tid] + psum[128 + tid];
            const float uu = __fdividef(MUC, s);
            u[tid] = uu; uh[tid] = __float2half_rn(uu * 64.0f);
        }
        __syncthreads();

        // ---- v-pass: colsum partials; write own + push to peer recv box
        const int buf = it & 1;
        #pragma unroll
        for (int n2 = 0; n2 < 2; ++n2) {
            float ca[4] = {0.f, 0.f, 0.f, 0.f};
            float cb[4] = {0.f, 0.f, 0.f, 0.f};
            #pragma unroll
            for (int t = 0; t < 8; t += 2) {
                const int k0 = t * 16 + 2 * lj;
                const int k1 = (t + 1) * 16 + 2 * lj;
                const uint32_t a00 = *(const uint32_t*)&uh[k0];
                const uint32_t a02 = *(const uint32_t*)&uh[k0 + 8];
                const uint32_t a10 = *(const uint32_t*)&uh[k1];
                const uint32_t a12 = *(const uint32_t*)&uh[k1 + 8];
                mma16816f(ca, a00, a00, a02, a02, bfr[n2][t][0], bfr[n2][t][1]);
                mma16816f(cb, a10, a10, a12, a12, bfr[n2][t+1][0], bfr[n2][t+1][1]);
            }
            if (lane < 4) {
                const int idx = (2 * w + n2) * 8 + 2 * lane;
                const float v0 = ca[0] + cb[0];
                const float v1 = ca[1] + cb[1];
                cso[idx]     = v0;
                cso[idx + 1] = v1;
                unsigned long long pk;
                asm("mov.b64 %0, {%1, %2};" : "=l"(pk) : "f"(v0), "f"(v1));
                asm volatile("st.shared::cluster.b64 [%0], %1;"
                             :: "r"(recv_peer + (uint32_t)((buf * NT + idx) * 4)), "l"(pk)
                             : "memory");
            }
        }
        if (lane < 4) {   // one release-arrive per producer thread (64/CTA)
            asm volatile("mbarrier.arrive.release.cluster.shared::cluster.b64 _, [%0];"
                         :: "r"(mbar_peer) : "memory");
        }
        __syncthreads();   // own cso visible to own readers

        if (tid < NT) {
            // wait for peer's 64 arrivals of this iteration (parity = it&1)
            uint32_t done;
            asm volatile("{ .reg .pred p; "
                         "mbarrier.try_wait.parity.acquire.cluster.shared::cta.b64 p, [%1], %2; "
                         "selp.b32 %0, 1, 0, p; }"
                         : "=r"(done) : "r"(mbar_local), "r"((uint32_t)(it & 1)) : "memory");
            while (!done) {
                asm volatile("{ .reg .pred p; "
                             "mbarrier.try_wait.parity.acquire.cluster.shared::cta.b64 p, [%1], %2, 0x989680; "
                             "selp.b32 %0, 1, 0, p; }"
                             : "=r"(done) : "r"(mbar_local), "r"((uint32_t)(it & 1)) : "memory");
            }
            const float own = cso[tid];
            const float pv  = recv[buf * NT + tid];
            const float s = rank == 0 ? (own + pv) : (pv + own);   // same order both CTAs
            const float nv = __fdividef(0.25f, s);                 // MUC*64 (uh scale cancels)
            v[tid] = nv; vh[tid] = __float2half_rn(nv);
        }
        __syncthreads();
    }

    // ---- transport loss over my 128 rows (warp w -> rows 8w..8w+7)
    float vl[8];
    {
        const float4 v0 = *(const float4*)&v[lane * 8];
        const float4 v1 = *(const float4*)&v[lane * 8 + 4];
        vl[0]=v0.x; vl[1]=v0.y; vl[2]=v0.z; vl[3]=v0.w;
        vl[4]=v1.x; vl[5]=v1.y; vl[6]=v1.z; vl[7]=v1.w;
    }
    float acc = 0.0f;
    #pragma unroll
    for (int r = 0; r < 8; ++r) {
        const int i = w * 8 + r;
        const float ui = u[i];
        const uint4 kw = *(const uint4*)(Ks + (size_t)i * NT + lane * 8);
        float kf[8];
        {
            float2 f;
            f = __half22float2(*(const __half2*)&kw.x); kf[0]=f.x; kf[1]=f.y;
            f = __half22float2(*(const __half2*)&kw.y); kf[2]=f.x; kf[3]=f.y;
            f = __half22float2(*(const __half2*)&kw.z); kf[4]=f.x; kf[5]=f.y;
            f = __half22float2(*(const __half2*)&kw.w); kf[6]=f.x; kf[7]=f.y;
        }
        #pragma unroll
        for (int q = 0; q < 8; ++q) {
            const float k = kf[q];
            if (k > 0.0f) {
                const float cost = (SHIFTF - __log2f(k)) * INV_K2;  // == 1 - dot
                acc = fmaf(ui * k * vl[q], cost, acc);
            }
        }
    }
    #pragma unroll
    for (int o = 16; o; o >>= 1) acc += __shfl_xor_sync(0xffffffffu, acc, o);
    if (lane == 0) red[w] = acc;
    __syncthreads();
    if (w == 0) {
        float s = (lane < 16) ? red[lane] : 0.0f;
        #pragma unroll
        for (int o = 16; o; o >>= 1) s += __shfl_xor_sync(0xffffffffu, s, o);
        if (lane == 0) {
            g_part[blockIdx.x] = s;
            __threadfence();
            if (atomicAdd(&g_ctr, 1u) == 2 * NB - 1) {   // last CTA: deterministic mean
                __threadfence();
                float tot = 0.0f;
                #pragma unroll
                for (int i = 0; i < 2 * NB; ++i) tot += __ldcg(&g_part[i]);
                out[0] = tot * (1.0f / NB);
            }
        }
    }
    // ensure no CTA exits while peer pushes may still target its smem
    asm volatile("barrier.cluster.arrive.aligned;" ::: "memory");
    asm volatile("barrier.cluster.wait.aligned;" ::: "memory");
}

// ============================================================================
extern "C" void kernel_launch(void* const* d_in, const int* in_sizes, int n_in,
                              void* d_out, int out_size)
{
    const float* pred = (const float*)d_in[0];
    const float* tgt  = (const float*)d_in[1];
    float* out = (float*)d_out;

    sample_kernel<<<dim3(NB, 2, 64), 256>>>(pred, tgt);

    cudaFuncSetAttribute(norm_transpose_kernel, cudaFuncAttributeMaxDynamicSharedMemorySize, NTR_SMEM);
    norm_transpose_kernel<<<2 * NB, 1024, NTR_SMEM>>>();

    cudaFuncSetAttribute(cost_kernel, cudaFuncAttributeMaxDynamicSharedMemorySize, COST_SMEM);
    cost_kernel<<<dim3(2, NB), 256, COST_SMEM>>>();

    cudaFuncSetAttribute(sinkhorn_kernel, cudaFuncAttributeMaxDynamicSharedMemorySize, SK_SMEM);
    sinkhorn_kernel<<<2 * NB, 512, SK_SMEM>>>(out);
}

// round 12
// speedup vs baseline: 1.2416x; 1.2416x over previous
#include <cuda_runtime.h>
#include <cuda_fp16.h>
#include <cuda_bf16.h>
#include <cstdint>

// ---------------- problem constants ----------------
#define NB   64
#define NT   256
#define NC   256
#define HW   4096
#define NITER 30

#define K2C     28.853900817779268f   // log2(e)/eps
#define INV_K2  0.03465735902799727f  // eps*ln2
#define SHIFTF  26.0f
#define MUC     (1.0f/256.0f)

// ---------------- scratch ----------------
__device__ __align__(16) __nv_bfloat16 g_tok[(size_t)2 * NB * NT * NC];  // [z][b][i][c]
__device__ __align__(16) __half        g_K[(size_t)NB * NT * NT];
__device__ float    g_part[2 * NB];
__device__ unsigned g_ctr;

__device__ __forceinline__ uint32_t smem_u32(const void* p) {
    uint32_t a;
    asm("{ .reg .u64 t; cvta.to.shared.u64 t, %1; cvt.u32.u64 %0, t; }" : "=r"(a) : "l"(p));
    return a;
}
__device__ __forceinline__ uint32_t h2_as_u32(__half lo, __half hi) {
    union { __half2 h; uint32_t u; } c;
    c.h = __halves2half2(lo, hi);
    return c.u;
}

// ============================================================================
// Kernel 1: FUSED streaming sampler + l2norm + transpose.
// grid (64, 2), 1024 threads. CTA reads its whole (b,z) plane (4MB) coalesced,
// extracts linspace samples into smem [c][i], normalizes, writes g_tok [i][c].
// ============================================================================
#define TSTR 264
#define GNF_SMEM (256 * TSTR * 2 + 4096 + 1024)

__global__ __launch_bounds__(1024, 1) void gather_norm_fused(
    const float* __restrict__ pred, const float* __restrict__ tgt)
{
    extern __shared__ unsigned char sm[];
    __nv_bfloat16* T = (__nv_bfloat16*)sm;               // [256 c][264] swizzled
    float* pss = (float*)(sm + 256 * TSTR * 2);          // [4][256]
    float* inv = (float*)(sm + 256 * TSTR * 2 + 4096);   // [256]

    const int b = blockIdx.x, z = blockIdx.y;
    if (threadIdx.x == 0 && (b | z) == 0) g_ctr = 0u;
    const int tid = threadIdx.x;
    const float DELTA = 4095.0f / 255.0f;

    const float4* __restrict__ src =
        (const float4*)((z ? tgt : pred) + (size_t)b * NC * HW);

    // thread tid owns float4 slot tid of every channel: window [tid*4, tid*4+4)
    const int p4 = tid * 4;
    const int cand = (int)(__fdividef((float)(p4 + 2), DELTA));
    int hit_i = -1, hit_off = 0;
    #pragma unroll
    for (int d = -1; d <= 1; ++d) {
        const int i = cand + d;
        if (i >= 0 && i < 256) {
            const int s = (int)(__fmul_rn((float)i, DELTA));  // exact ref trunc
            if (s >= p4 && s < p4 + 4) { hit_i = i; hit_off = s - p4; }
        }
    }
    const int ibs = (hit_i >= 0) ? ((hit_i >> 3) << 0) : 0;
    const int ios = (hit_i >= 0) ? (hit_i & 7) : 0;

    #pragma unroll 2
    for (int c4 = 0; c4 < NC; c4 += 4) {
        float4 f[4];
        #pragma unroll
        for (int q = 0; q < 4; ++q) f[q] = __ldcs(&src[(size_t)(c4 + q) * 1024 + tid]);
        if (hit_i >= 0) {
            #pragma unroll
            for (int q = 0; q < 4; ++q) {
                const int c = c4 + q;
                const float* fv = (const float*)&f[q];
                T[c * TSTR + (((ibs) ^ ((c >> 3) & 7)) << 3) + ios] =
                    __float2bfloat16(fv[hit_off]);
            }
        }
    }
    __syncthreads();

    {   // sum of squares per token
        const int i = tid & 255, part = tid >> 8;
        const int ib = i >> 3, io = i & 7;
        float ss = 0.0f;
        #pragma unroll 8
        for (int cc = 0; cc < 64; ++cc) {
            const int c = part * 64 + cc;
            const float x = __bfloat162float(
                T[c * TSTR + ((ib ^ ((c >> 3) & 7)) << 3) + io]);
            ss = fmaf(x, x, ss);
        }
        pss[part * 256 + i] = ss;
    }
    __syncthreads();
    if (tid < 256) {
        const float ss = pss[tid] + pss[256 + tid] + pss[512 + tid] + pss[768 + tid];
        inv[tid] = __fdividef(1.0f, fmaxf(sqrtf(ss), 1e-12f));
    }
    __syncthreads();

    uint4* __restrict__ dst = (uint4*)(g_tok + ((size_t)z * NB + b) * NT * NC);
    #pragma unroll
    for (int k = 0; k < 8; ++k) {
        const int idx = tid + k * 1024;
        const int i = idx >> 5, c0 = (idx & 31) * 8;
        const float sc = inv[i];
        const int ib = i >> 3, io = i & 7;
        union { uint4 u; __nv_bfloat16 h[8]; } o;
        #pragma unroll
        for (int j = 0; j < 8; ++j) {
            const int c = c0 + j;
            const float x = __bfloat162float(
                T[c * TSTR + ((ib ^ ((c >> 3) & 7)) << 3) + io]);
            o.h[j] = __float2bfloat16(x * sc);
        }
        dst[idx] = o.u;
    }
}

// ============================================================================
// Kernel 2: cost GEMM via mma.sync bf16 (unchanged).
// ============================================================================
#define SPAD 264
#define COST_SMEM ((128 + 256) * SPAD * 2)

__device__ __forceinline__ void mma16816bf(float* c, uint32_t a0, uint32_t a1,
                                           uint32_t a2, uint32_t a3,
                                           uint32_t b0, uint32_t b1) {
    asm volatile(
        "mma.sync.aligned.m16n8k16.row.col.f32.bf16.bf16.f32 "
        "{%0,%1,%2,%3}, {%4,%5,%6,%7}, {%8,%9}, {%0,%1,%2,%3};"
        : "+f"(c[0]), "+f"(c[1]), "+f"(c[2]), "+f"(c[3])
        : "r"(a0), "r"(a1), "r"(a2), "r"(a3), "r"(b0), "r"(b1));
}

__global__ __launch_bounds__(256, 1) void cost_kernel()
{
    extern __shared__ char smem[];
    __nv_bfloat16* As = (__nv_bfloat16*)smem;
    __nv_bfloat16* Bs = (__nv_bfloat16*)(smem + 128 * SPAD * 2);

    const int mh = blockIdx.x;
    const int b  = blockIdx.y;
    const int tid = threadIdx.x, w = tid >> 5, lane = tid & 31;

    const uint4* __restrict__ Ag =
        (const uint4*)(g_tok + ((size_t)b * NT + (size_t)mh * 128) * NC);
    #pragma unroll
    for (int it = 0; it < 16; ++it) {
        const int idx = tid + it * 256;
        *(uint4*)(As + (idx >> 5) * SPAD + (idx & 31) * 8) = Ag[idx];
    }
    const uint4* __restrict__ Bg = (const uint4*)(g_tok + ((size_t)(NB + b)) * NT * NC);
    #pragma unroll
    for (int it = 0; it < 32; ++it) {
        const int idx = tid + it * 256;
        *(uint4*)(Bs + (idx >> 5) * SPAD + (idx & 31) * 8) = Bg[idx];
    }
    __syncthreads();

    const int r0 = w * 16;
    const int lr = lane >> 2;
    const int lj = lane & 3;

    const __nv_bfloat16* A0 = As + (r0 + lr) * SPAD + lj * 2;
    const __nv_bfloat16* A8 = A0 + 8 * SPAD;
    const __nv_bfloat16* B0 = Bs + lr * SPAD + lj * 2;

    __half* __restrict__ K0 = g_K + ((size_t)b * NT + (size_t)(mh * 128 + r0 + lr)) * NT;
    __half* __restrict__ K8 = K0 + 8 * NT;

    #pragma unroll
    for (int h = 0; h < 2; ++h) {
        float c[16][4];
        #pragma unroll
        for (int nt = 0; nt < 16; ++nt)
            c[nt][0] = c[nt][1] = c[nt][2] = c[nt][3] = 0.0f;

        #pragma unroll
        for (int kc = 0; kc < 16; ++kc) {
            const int ko = kc * 16;
            const uint32_t a0 = *(const uint32_t*)(A0 + ko);
            const uint32_t a1 = *(const uint32_t*)(A8 + ko);
            const uint32_t a2 = *(const uint32_t*)(A0 + ko + 8);
            const uint32_t a3 = *(const uint32_t*)(A8 + ko + 8);
            #pragma unroll
            for (int nt = 0; nt < 16; ++nt) {
                const __nv_bfloat16* bp = B0 + (h * 128 + nt * 8) * SPAD + ko;
                mma16816bf(c[nt], a0, a1, a2, a3,
                           *(const uint32_t*)bp, *(const uint32_t*)(bp + 8));
            }
        }

        #pragma unroll
        for (int nt = 0; nt < 16; ++nt) {
            const int col = h * 128 + nt * 8 + lj * 2;
            *(__half2*)(K0 + col) = __halves2half2(
                __float2half_rn(exp2f(fmaf(c[nt][0] - 1.0f, K2C, SHIFTF))),
                __float2half_rn(exp2f(fmaf(c[nt][1] - 1.0f, K2C, SHIFTF))));
            *(__half2*)(K8 + col) = __halves2half2(
                __float2half_rn(exp2f(fmaf(c[nt][2] - 1.0f, K2C, SHIFTF))),
                __float2half_rn(exp2f(fmaf(c[nt][3] - 1.0f, K2C, SHIFTF))));
        }
    }
}

// ============================================================================
// Kernel 3: Sinkhorn, WARP-SPECIALIZED.
//  warps 0-7  (row warps): full-K row fragments -> rowsums + u-update fused
//  warps 8-15 (col warps): full-local-K col fragments -> colsums + DSMEM push
//                          + peer wait + v-update fused
// 2 barriers + 1 mbarrier wait per iteration. frag[] shared by role.
// ============================================================================
#define SK_KS    0
#define SK_RECV  65536                 // [2][256] f32 peer-pushed colsums
#define SK_V     (SK_RECV + 2048)      // [256] f32
#define SK_U     (SK_V + 1024)         // [128] f32
#define SK_UH    (SK_U + 512)          // [128] f16 (scaled x64)
#define SK_VH    (SK_UH + 256)         // [256] f16
#define SK_RED   (SK_VH + 512)         // [16] f32 (pad)
#define SK_MBAR  (SK_RED + 128)
#define SK_SMEM  (SK_MBAR + 16)

__device__ __forceinline__ void mma16816f(float* c, uint32_t a0, uint32_t a1,
                                          uint32_t a2, uint32_t a3,
                                          uint32_t b0, uint32_t b1) {
    asm volatile(
        "mma.sync.aligned.m16n8k16.row.col.f32.f16.f16.f32 "
        "{%0,%1,%2,%3}, {%4,%5,%6,%7}, {%8,%9}, {%0,%1,%2,%3};"
        : "+f"(c[0]), "+f"(c[1]), "+f"(c[2]), "+f"(c[3])
        : "r"(a0), "r"(a1), "r"(a2), "r"(a3), "r"(b0), "r"(b1));
}

__global__ __launch_bounds__(512, 1) __cluster_dims__(2, 1, 1)
void sinkhorn_kernel(float* __restrict__ out)
{
    extern __shared__ unsigned char sm[];
    __half* Ks   = (__half*)(sm + SK_KS);      // [128][256] local rows
    float*  recv = (float*)(sm + SK_RECV);
    float*  v    = (float*)(sm + SK_V);
    float*  u    = (float*)(sm + SK_U);
    __half* uh   = (__half*)(sm + SK_UH);
    __half* vh   = (__half*)(sm + SK_VH);
    float*  red  = (float*)(sm + SK_RED);

    const int rank = blockIdx.x & 1;
    const int b    = blockIdx.x >> 1;
    const int tid  = threadIdx.x;
    const int w    = tid >> 5, lane = tid & 31;
    const int lr4  = lane >> 2, lj = lane & 3;

    const uint32_t mbar_local = smem_u32(sm + SK_MBAR);
    uint32_t recv_peer, mbar_peer;
    {
        const uint32_t recv_local = smem_u32(recv);
        asm("mapa.shared::cluster.u32 %0, %1, %2;" : "=r"(recv_peer)
            : "r"(recv_local), "r"(rank ^ 1));
        asm("mapa.shared::cluster.u32 %0, %1, %2;" : "=r"(mbar_peer)
            : "r"(mbar_local), "r"(rank ^ 1));
    }

    if (tid == 0) {
        asm volatile("mbarrier.init.shared.b64 [%0], %1;"
                     :: "r"(mbar_local), "r"(32u) : "memory");
    }

    {   // load my 128 rows of K' (64 KB)
        const uint4* gk = (const uint4*)(g_K + ((size_t)b * NT + (size_t)rank * 128) * NT);
        uint4* sk = (uint4*)Ks;
        #pragma unroll
        for (int q = 0; q < 8; ++q) sk[tid + q * 512] = gk[tid + q * 512];
    }
    if (tid < NT) { v[tid] = 1.0f; vh[tid] = __float2half_rn(1.0f); }
    __syncthreads();

    // cluster sync once: peer mbarrier init visible before any remote push
    asm volatile("barrier.cluster.arrive.aligned;" ::: "memory");
    asm volatile("barrier.cluster.wait.aligned;" ::: "memory");

    // ---- role-shared fragment storage (disjoint indexing per role) ----
    uint32_t frag[64];
    const bool roww = (w < 8);
    const int rt = w;           // row warp: rows rt*16..+15
    const int wc = w - 8;       // col warp: ntiles wc*4..wc*4+3

    if (roww) {
        #pragma unroll
        for (int t = 0; t < 16; ++t) {
            const int kt = t * 16 + 2 * lj;
            frag[t*4+0] = *(const uint32_t*)&Ks[(rt * 16 + lr4) * NT + kt];
            frag[t*4+1] = *(const uint32_t*)&Ks[(rt * 16 + 8 + lr4) * NT + kt];
            frag[t*4+2] = *(const uint32_t*)&Ks[(rt * 16 + lr4) * NT + kt + 8];
            frag[t*4+3] = *(const uint32_t*)&Ks[(rt * 16 + 8 + lr4) * NT + kt + 8];
        }
    } else {
        #pragma unroll
        for (int j = 0; j < 4; ++j) {
            const int col = (wc * 4 + j) * 8 + lr4;
            #pragma unroll
            for (int t = 0; t < 8; ++t) {
                const int k0 = t * 16 + 2 * lj;
                frag[(j*8+t)*2+0] = h2_as_u32(Ks[(size_t)k0 * NT + col],
                                              Ks[(size_t)(k0 + 1) * NT + col]);
                frag[(j*8+t)*2+1] = h2_as_u32(Ks[(size_t)(k0 + 8) * NT + col],
                                              Ks[(size_t)(k0 + 9) * NT + col]);
            }
        }
    }

    for (int it = 0; it < NITER; ++it) {
        __syncthreads();   // vh(it) visible to row warps
        if (roww) {
            // ---- u-pass: full-k rowsums, 4 independent chains of depth 4
            float cc[4][4] = {};
            #pragma unroll
            for (int t = 0; t < 16; t += 4) {
                #pragma unroll
                for (int q = 0; q < 4; ++q) {
                    const int kt = (t + q) * 16 + 2 * lj;
                    mma16816f(cc[q],
                              frag[(t+q)*4+0], frag[(t+q)*4+1],
                              frag[(t+q)*4+2], frag[(t+q)*4+3],
                              *(const uint32_t*)&vh[kt],
                              *(const uint32_t*)&vh[kt + 8]);
                }
            }
            if (lj == 0) {
                const float s0 = (cc[0][0] + cc[1][0]) + (cc[2][0] + cc[3][0]);
                const float s2 = (cc[0][2] + cc[1][2]) + (cc[2][2] + cc[3][2]);
                const float u0 = __fdividef(MUC, s0);
                const float u2 = __fdividef(MUC, s2);
                const int i0 = rt * 16 + lr4;
                u[i0] = u0;      uh[i0] = __float2half_rn(u0 * 64.0f);
                u[i0 + 8] = u2;  uh[i0 + 8] = __float2half_rn(u2 * 64.0f);
            }
        }
        __syncthreads();   // uh visible to col warps
        if (!roww) {
            const int buf = it & 1;
            // ---- v-pass: 4 ntiles, 4 independent chains of depth 8
            float cc[4][4] = {};
            #pragma unroll
            for (int t = 0; t < 8; ++t) {
                const int k0 = t * 16 + 2 * lj;
                const uint32_t a0 = *(const uint32_t*)&uh[k0];
                const uint32_t a2 = *(const uint32_t*)&uh[k0 + 8];
                #pragma unroll
                for (int j = 0; j < 4; ++j)
                    mma16816f(cc[j], a0, a0, a2, a2,
                              frag[(j*8+t)*2+0], frag[(j*8+t)*2+1]);
            }
            if (lane < 4) {   // lr4==0, lj==lane: push + update cols 2lj,2lj+1 per ntile
                #pragma unroll
                for (int j = 0; j < 4; ++j) {
                    const int idx = (wc * 4 + j) * 8 + 2 * lane;
                    unsigned long long pk;
                    asm("mov.b64 %0, {%1, %2};" : "=l"(pk) : "f"(cc[j][0]), "f"(cc[j][1]));
                    asm volatile("st.shared::cluster.b64 [%0], %1;"
                                 :: "r"(recv_peer + (uint32_t)((buf * NT + idx) * 4)), "l"(pk)
                                 : "memory");
                }
                asm volatile("mbarrier.arrive.release.cluster.shared::cluster.b64 _, [%0];"
                             :: "r"(mbar_peer) : "memory");
                // wait for peer's 32 arrivals this iteration
                uint32_t done;
                asm volatile("{ .reg .pred p; "
                             "mbarrier.try_wait.parity.acquire.cluster.shared::cta.b64 p, [%1], %2; "
                             "selp.b32 %0, 1, 0, p; }"
                             : "=r"(done) : "r"(mbar_local), "r"((uint32_t)buf) : "memory");
                while (!done) {
                    asm volatile("{ .reg .pred p; "
                                 "mbarrier.try_wait.parity.acquire.cluster.shared::cta.b64 p, [%1], %2, 0x989680; "
                                 "selp.b32 %0, 1, 0, p; }"
                                 : "=r"(done) : "r"(mbar_local), "r"((uint32_t)buf) : "memory");
                }
                #pragma unroll
                for (int j = 0; j < 4; ++j) {
                    const int idx = (wc * 4 + j) * 8 + 2 * lane;
                    const float p0 = recv[buf * NT + idx];
                    const float p1 = recv[buf * NT + idx + 1];
                    const float s0 = rank == 0 ? (cc[j][0] + p0) : (p0 + cc[j][0]);
                    const float s1 = rank == 0 ? (cc[j][1] + p1) : (p1 + cc[j][1]);
                    const float nv0 = __fdividef(0.25f, s0);   // MUC*64 (uh scale cancels)
                    const float nv1 = __fdividef(0.25f, s1);
                    v[idx] = nv0;     vh[idx] = __float2half_rn(nv0);
                    v[idx + 1] = nv1; vh[idx + 1] = __float2half_rn(nv1);
                }
            }
        }
    }
    __syncthreads();   // final u, v visible to all

    // ---- transport loss over my 128 rows (warp w -> rows 8w..8w+7)
    float vl[8];
    {
        const float4 v0 = *(const float4*)&v[lane * 8];
        const float4 v1 = *(const float4*)&v[lane * 8 + 4];
        vl[0]=v0.x; vl[1]=v0.y; vl[2]=v0.z; vl[3]=v0.w;
        vl[4]=v1.x; vl[5]=v1.y; vl[6]=v1.z; vl[7]=v1.w;
    }
    float acc = 0.0f;
    #pragma unroll
    for (int r = 0; r < 8; ++r) {
        const int i = w * 8 + r;
        const float ui = u[i];
        const uint4 kw = *(const uint4*)(Ks + (size_t)i * NT + lane * 8);
        float kf[8];
        {
            float2 f;
            f = __half22float2(*(const __half2*)&kw.x); kf[0]=f.x; kf[1]=f.y;
            f = __half22float2(*(const __half2*)&kw.y); kf[2]=f.x; kf[3]=f.y;
            f = __half22float2(*(const __half2*)&kw.z); kf[4]=f.x; kf[5]=f.y;
            f = __half22float2(*(const __half2*)&kw.w); kf[6]=f.x; kf[7]=f.y;
        }
        #pragma unroll
        for (int q = 0; q < 8; ++q) {
            const float k = kf[q];
            if (k > 0.0f) {
                const float cost = (SHIFTF - __log2f(k)) * INV_K2;  // == 1 - dot
                acc = fmaf(ui * k * vl[q], cost, acc);
            }
        }
    }
    #pragma unroll
    for (int o = 16; o; o >>= 1) acc += __shfl_xor_sync(0xffffffffu, acc, o);
    if (lane == 0) red[w] = acc;
    __syncthreads();
    if (w == 0) {
        float s = (lane < 16) ? red[lane] : 0.0f;
        #pragma unroll
        for (int o = 16; o; o >>= 1) s += __shfl_xor_sync(0xffffffffu, s, o);
        if (lane == 0) {
            g_part[blockIdx.x] = s;
            __threadfence();
            if (atomicAdd(&g_ctr, 1u) == 2 * NB - 1) {   // last CTA: deterministic mean
                __threadfence();
                float tot = 0.0f;
                #pragma unroll
                for (int i = 0; i < 2 * NB; ++i) tot += __ldcg(&g_part[i]);
                out[0] = tot * (1.0f / NB);
            }
        }
    }
    // no CTA may exit while peer pushes could still target its smem
    asm volatile("barrier.cluster.arrive.aligned;" ::: "memory");
    asm volatile("barrier.cluster.wait.aligned;" ::: "memory");
}

// ============================================================================
extern "C" void kernel_launch(void* const* d_in, const int* in_sizes, int n_in,
                              void* d_out, int out_size)
{
    const float* pred = (const float*)d_in[0];
    const float* tgt  = (const float*)d_in[1];
    float* out = (float*)d_out;

    cudaFuncSetAttribute(gather_norm_fused, cudaFuncAttributeMaxDynamicSharedMemorySize, GNF_SMEM);
    gather_norm_fused<<<dim3(NB, 2), 1024, GNF_SMEM>>>(pred, tgt);

    cudaFuncSetAttribute(cost_kernel, cudaFuncAttributeMaxDynamicSharedMemorySize, COST_SMEM);
    cost_kernel<<<dim3(2, NB), 256, COST_SMEM>>>();

    cudaFuncSetAttribute(sinkhorn_kernel, cudaFuncAttributeMaxDynamicSharedMemorySize, SK_SMEM);
    sinkhorn_kernel<<<2 * NB, 512, SK_SMEM>>>(out);
}